// round 4
// baseline (speedup 1.0000x reference)
#include <cuda_runtime.h>
#include <math.h>

#define D 64
#define S 16
#define NB 16   // batches per CTA in k_main

// ---------------- device scratch (static, no runtime alloc) ----------------
__device__ float g_Cr[64 * 64];
__device__ float g_Ci[64 * 64];
__device__ float g_U[16384 * 128];   // per-batch u vector (real 64 | imag 64)
__device__ int   g_count;

// ---------------- kernel 0: C = Wq^T * conj(Wk), zero counter ----------------
__global__ void k_prep(const float* __restrict__ wqr, const float* __restrict__ wqi,
                       const float* __restrict__ wkr, const float* __restrict__ wki) {
    int d = blockIdx.x;   // 64 blocks
    int e = threadIdx.x;  // 64 threads
    if (d == 0 && e == 0) g_count = 0;
    float cr = 0.f, ci = 0.f;
#pragma unroll 8
    for (int j = 0; j < 64; ++j) {
        float aqr = wqr[j * 64 + d], aqi = wqi[j * 64 + d];
        float bkr = wkr[j * 64 + e], bki = wki[j * 64 + e];
        cr = fmaf(aqr, bkr, cr); cr = fmaf(aqi, bki, cr);
        ci = fmaf(aqi, bkr, ci); ci = fmaf(-aqr, bki, ci);
    }
    g_Cr[d * 64 + e] = cr;
    g_Ci[d * 64 + e] = ci;
}

// ---------------- kernel 1: main fused per-batch pipeline ----------------
__global__ __launch_bounds__(256, 4) void k_main(
    const float* __restrict__ zr, const float* __restrict__ zi,
    const float* __restrict__ mem, const float* __restrict__ ptrv,
    const float* __restrict__ ctrl, float* __restrict__ out,
    int o_mem, int o_ptr)
{
    extern __shared__ float sm[];
    float* sCr   = sm;                   // 4096
    float* sCi   = sCr + 4096;           // 4096
    float* sMr   = sCi + 4096;           // 16*65
    float* sMi   = sMr + 16 * 65;        // 16*65
    float* sPr   = sMi + 16 * 65;        // 16*65
    float* sPi   = sPr + 16 * 65;        // 16*65
    float* sAttn = sPi + 16 * 65;        // 16*17
    float* sPtr  = sAttn + 16 * 17;      // 16
    float* sNp   = sPtr + 16;            // 16
    float* sCw   = sNp + 16;             // 16

    const int tid = threadIdx.x;
    for (int i = tid; i < 4096; i += 256) { sCr[i] = g_Cr[i]; sCi[i] = g_Ci[i]; }

    const int sg = tid >> 4;   // 0..15  (s row)
    const int ln = tid & 15;   // 0..15  (column group)
    int cnt = 0;

    for (int bl = 0; bl < NB; ++bl) {
        const int b = blockIdx.x * NB + bl;
        __syncthreads();  // protects smem reuse across batches (and C load, 1st iter)

        // gates (redundant per thread; L1-broadcast loads)
        float c0 = ctrl[b * 3 + 0], c1 = ctrl[b * 3 + 1], c2 = ctrl[b * 3 + 2];
        float g0 = 1.f / (1.f + expf(-c0));
        float g1 = 1.f / (1.f + expf(-c1));
        float g2 = 1.f / (1.f + expf(-c2));
        float inv = 1.f / (g0 + g1 + g2 + 1e-6f);
        float push = g0 * inv, pop = g1 * inv, stay = g2 * inv;

        if (tid < 16) sPtr[tid] = ptrv[b * 16 + tid];

        // mem_new = mem*(1-push) + push*z_flat ; write out + stage into smem
#pragma unroll
        for (int it = 0; it < 8; ++it) {
            int i  = tid + it * 256;
            int s_ = i >> 7, d2 = i & 127;
            float zv = (d2 < 64) ? zr[b * 64 + d2] : zi[b * 64 + (d2 - 64)];
            float mv = mem[b * 2048 + i];
            float nv = mv * (1.f - push) + push * zv;
            out[o_mem + b * 2048 + i] = nv;
            if (d2 < 64) sMr[s_ * 65 + d2] = nv;
            else         sMi[s_ * 65 + (d2 - 64)] = nv;
        }
        __syncthreads();

        // new_ptr (roll-mix) + slot count
        if (tid < 16) {
            float np = push * sPtr[(tid + 15) & 15] + pop * sPtr[(tid + 1) & 15]
                     + stay * sPtr[tid];
            sNp[tid] = np;
            out[o_ptr + b * 16 + tid] = np;
            unsigned bal = __ballot_sync(0xFFFFu, np > 0.1f);
            if (tid == 0) cnt += __popc(bal);
        }

        // P = M * C (complex 16x64 = 16x64 * 64x64). thread -> (s=sg, e=ln+16k)
        float pr0 = 0, pr1 = 0, pr2 = 0, pr3 = 0;
        float pi0 = 0, pi1 = 0, pi2 = 0, pi3 = 0;
#pragma unroll 4
        for (int d = 0; d < 64; ++d) {
            float mr = sMr[sg * 65 + d], mi = sMi[sg * 65 + d];
            float cr, ci;
            cr = sCr[d * 64 + ln];        ci = sCi[d * 64 + ln];
            pr0 = fmaf(mr, cr, pr0); pr0 = fmaf(-mi, ci, pr0);
            pi0 = fmaf(mr, ci, pi0); pi0 = fmaf(mi, cr, pi0);
            cr = sCr[d * 64 + ln + 16];   ci = sCi[d * 64 + ln + 16];
            pr1 = fmaf(mr, cr, pr1); pr1 = fmaf(-mi, ci, pr1);
            pi1 = fmaf(mr, ci, pi1); pi1 = fmaf(mi, cr, pi1);
            cr = sCr[d * 64 + ln + 32];   ci = sCi[d * 64 + ln + 32];
            pr2 = fmaf(mr, cr, pr2); pr2 = fmaf(-mi, ci, pr2);
            pi2 = fmaf(mr, ci, pi2); pi2 = fmaf(mi, cr, pi2);
            cr = sCr[d * 64 + ln + 48];   ci = sCi[d * 64 + ln + 48];
            pr3 = fmaf(mr, cr, pr3); pr3 = fmaf(-mi, ci, pr3);
            pi3 = fmaf(mr, ci, pi3); pi3 = fmaf(mi, cr, pi3);
        }
        sPr[sg * 65 + ln]      = pr0;  sPi[sg * 65 + ln]      = pi0;
        sPr[sg * 65 + ln + 16] = pr1;  sPi[sg * 65 + ln + 16] = pi1;
        sPr[sg * 65 + ln + 32] = pr2;  sPi[sg * 65 + ln + 32] = pi2;
        sPr[sg * 65 + ln + 48] = pr3;  sPi[sg * 65 + ln + 48] = pi3;
        __syncthreads();

        // scores[s,t] = scale * sum_d (Pr[s,d]*Mr[t,d] + Pi[s,d]*Mi[t,d])
        float acc = 0.f;
#pragma unroll 8
        for (int d2 = 0; d2 < 64; ++d2) {
            acc = fmaf(sPr[sg * 65 + d2], sMr[ln * 65 + d2], acc);
            acc = fmaf(sPi[sg * 65 + d2], sMi[ln * 65 + d2], acc);
        }
        acc *= 0.125f;  // D^-0.5

        // softmax over t within each 16-lane group
        float mx = acc;
        mx = fmaxf(mx, __shfl_xor_sync(0xFFFFFFFFu, mx, 8, 16));
        mx = fmaxf(mx, __shfl_xor_sync(0xFFFFFFFFu, mx, 4, 16));
        mx = fmaxf(mx, __shfl_xor_sync(0xFFFFFFFFu, mx, 2, 16));
        mx = fmaxf(mx, __shfl_xor_sync(0xFFFFFFFFu, mx, 1, 16));
        float ex = expf(acc - mx);
        float sme = ex;
        sme += __shfl_xor_sync(0xFFFFFFFFu, sme, 8, 16);
        sme += __shfl_xor_sync(0xFFFFFFFFu, sme, 4, 16);
        sme += __shfl_xor_sync(0xFFFFFFFFu, sme, 2, 16);
        sme += __shfl_xor_sync(0xFFFFFFFFu, sme, 1, 16);
        sAttn[sg * 17 + ln] = ex / sme;
        __syncthreads();

        // cw[t] = sum_s np[s] * attn[s,t]
        if (tid < 16) {
            float a = 0.f;
#pragma unroll
            for (int s2 = 0; s2 < 16; ++s2) a = fmaf(sNp[s2], sAttn[s2 * 17 + tid], a);
            sCw[tid] = a;
        }
        __syncthreads();

        // u[d] = sum_t cw[t] * M[t,d]  (real | imag)
        if (tid < 128) {
            int d2 = tid & 63;
            const float* Mrow = (tid < 64) ? sMr : sMi;
            float a = 0.f;
#pragma unroll
            for (int t2 = 0; t2 < 16; ++t2) a = fmaf(sCw[t2], Mrow[t2 * 65 + d2], a);
            g_U[b * 128 + (tid >> 6) * 64 + d2] = a;
        }
    }
    if (tid == 0) atomicAdd(&g_count, cnt);
}

// ---------------- kernel 2: z_read = u * Wv^T (complex) ----------------
__global__ __launch_bounds__(256) void k_read(const float* __restrict__ wvr,
                                              const float* __restrict__ wvi,
                                              float* __restrict__ out, int o_zi)
{
    __shared__ float sWr[64 * 65];
    __shared__ float sWi[64 * 65];
    __shared__ float sU[16 * 128];

    const int tid = threadIdx.x;
    for (int i = tid; i < 4096; i += 256) {
        int r = i >> 6, c = i & 63;
        sWr[r * 65 + c] = wvr[i];
        sWi[r * 65 + c] = wvi[i];
    }
    const int b0 = blockIdx.x * 16;
    for (int i = tid; i < 2048; i += 256) sU[i] = g_U[b0 * 128 + i];
    __syncthreads();

    const int bl = tid >> 4;   // local batch 0..15
    const int ln = tid & 15;   // j group
    float rr[4] = {0, 0, 0, 0}, ri[4] = {0, 0, 0, 0};
#pragma unroll 4
    for (int d = 0; d < 64; ++d) {
        float ur = sU[bl * 128 + d];
        float ui = sU[bl * 128 + 64 + d];
#pragma unroll
        for (int k = 0; k < 4; ++k) {
            int j = ln + 16 * k;
            float wr = sWr[j * 65 + d], wi = sWi[j * 65 + d];
            rr[k] = fmaf(ur, wr, rr[k]); rr[k] = fmaf(-ui, wi, rr[k]);
            ri[k] = fmaf(ui, wr, ri[k]); ri[k] = fmaf(ur, wi, ri[k]);
        }
    }
    const int b = b0 + bl;
#pragma unroll
    for (int k = 0; k < 4; ++k) {
        out[b * 64 + ln + 16 * k]        = rr[k];
        out[o_zi + b * 64 + ln + 16 * k] = ri[k];
    }
}

// ---------------- kernel 3: active_slots scalar ----------------
__global__ void k_final(float* __restrict__ out, int o_scal, float invB) {
    out[o_scal] = (float)g_count * invB;
}

// ---------------- launch ----------------
extern "C" void kernel_launch(void* const* d_in, const int* in_sizes, int n_in,
                              void* d_out, int out_size) {
    const float* zr   = (const float*)d_in[0];
    const float* zi   = (const float*)d_in[1];
    const float* mem  = (const float*)d_in[2];
    const float* ptrv = (const float*)d_in[3];
    const float* ctrl = (const float*)d_in[4];
    const float* wqr  = (const float*)d_in[5];
    const float* wqi  = (const float*)d_in[6];
    const float* wkr  = (const float*)d_in[7];
    const float* wki  = (const float*)d_in[8];
    const float* wvr  = (const float*)d_in[9];
    const float* wvi  = (const float*)d_in[10];
    float* out = (float*)d_out;

    const int B = in_sizes[0] / 64;               // 16384
    const int o_mem  = 2 * B * 64;                // after z_read_real|imag
    const int o_ptr  = o_mem + B * 2048;          // after mem_new
    const int o_scal = o_ptr + B * 16;            // active_slots scalar

    const int smem_bytes = (4096 * 2 + 4 * 16 * 65 + 16 * 17 + 48) * (int)sizeof(float);
    cudaFuncSetAttribute(k_main, cudaFuncAttributeMaxDynamicSharedMemorySize, 64 * 1024);

    k_prep<<<64, 64>>>(wqr, wqi, wkr, wki);
    k_main<<<B / NB, 256, smem_bytes>>>(zr, zi, mem, ptrv, ctrl, out, o_mem, o_ptr);
    k_read<<<B / 16, 256>>>(wvr, wvi, out, B * 64);
    k_final<<<1, 1>>>(out, o_scal, 1.f / (float)B);
}

// round 5
// speedup vs baseline: 1.3824x; 1.3824x over previous
#include <cuda_runtime.h>
#include <math.h>

#define D 64
#define S 16
#define NB 16   // batches per CTA in k_main (processed in pairs)

// ---------------- device scratch (static, no runtime alloc) ----------------
// C stored PACKED along d: float pair {C[2*d2][e], C[2*d2+1][e]} at offset d2*128 + 2*e
__device__ float g_Cr[64 * 64];
__device__ float g_Ci[64 * 64];
__device__ float g_U[16384 * 128];   // per-batch u vector (real 64 | imag 64)
__device__ int   g_count;

// ---------------- f32x2 packed helpers ----------------
__device__ __forceinline__ void ffma2(unsigned long long& d_,
                                      unsigned long long a_, unsigned long long b_) {
    asm("fma.rn.f32x2 %0, %1, %2, %0;" : "+l"(d_) : "l"(a_), "l"(b_));
}
__device__ __forceinline__ float hadd2(unsigned long long v) {
    float lo, hi;
    asm("mov.b64 {%0, %1}, %2;" : "=f"(lo), "=f"(hi) : "l"(v));
    return lo + hi;
}
__device__ __forceinline__ unsigned long long L64(const float* p) {
    return *reinterpret_cast<const unsigned long long*>(p);
}

// ---------------- kernel 0: C = Wq^T * conj(Wk) (packed layout), zero counter ----------------
__global__ void k_prep(const float* __restrict__ wqr, const float* __restrict__ wqi,
                       const float* __restrict__ wkr, const float* __restrict__ wki) {
    int d = blockIdx.x;   // 64 blocks
    int e = threadIdx.x;  // 64 threads
    if (d == 0 && e == 0) g_count = 0;
    float cr = 0.f, ci = 0.f;
#pragma unroll 8
    for (int j = 0; j < 64; ++j) {
        float aqr = wqr[j * 64 + d], aqi = wqi[j * 64 + d];
        float bkr = wkr[j * 64 + e], bki = wki[j * 64 + e];
        cr = fmaf(aqr, bkr, cr); cr = fmaf(aqi, bki, cr);
        ci = fmaf(aqi, bkr, ci); ci = fmaf(-aqr, bki, ci);
    }
    int idx = (d >> 1) * 128 + 2 * e + (d & 1);   // d-pair packed
    g_Cr[idx] = cr;
    g_Ci[idx] = ci;
}

// ---------------- kernel 1: main fused per-batch pipeline (2-batch blocked) ----------------
__global__ __launch_bounds__(256, 2) void k_main(
    const float* __restrict__ zr, const float* __restrict__ zi,
    const float* __restrict__ mem, const float* __restrict__ ptrv,
    const float* __restrict__ ctrl, float* __restrict__ out,
    int o_mem, int o_ptr)
{
    extern __shared__ float sm[];
    float* sCr   = sm;                 // 4096 (packed d-pairs)
    float* sCi   = sCr + 4096;         // 4096
    float* sMr   = sCi + 4096;         // 2 * 16*66 = 2112
    float* sMi   = sMr + 2112;         // 2112
    float* sMn   = sMi + 2112;         // 2112 (negated imag)
    float* sPr   = sMn + 2112;         // 2112
    float* sPi   = sPr + 2112;         // 2112
    float* sAttn = sPi + 2112;         // 2*16*17 = 544
    float* sPtr  = sAttn + 544;        // 32
    float* sNp   = sPtr + 32;          // 32
    float* sCw   = sNp + 32;           // 32

    const int tid = threadIdx.x;
    for (int i = tid; i < 4096; i += 256) { sCr[i] = g_Cr[i]; sCi[i] = g_Ci[i]; }

    const int sg = tid >> 4;   // 0..15 (s row)
    const int ln = tid & 15;   // 0..15 (column group)
    int cnt = 0;

    for (int bl = 0; bl < NB / 2; ++bl) {
        const int b0 = blockIdx.x * NB + bl * 2;
        __syncthreads();   // protects smem reuse across pairs (and C load, 1st iter)

        // gates for both batches (redundant per thread; L1-broadcast loads)
        float push[2], pop[2], stay[2];
#pragma unroll
        for (int q = 0; q < 2; ++q) {
            int b = b0 + q;
            float g0 = 1.f / (1.f + expf(-ctrl[b * 3 + 0]));
            float g1 = 1.f / (1.f + expf(-ctrl[b * 3 + 1]));
            float g2 = 1.f / (1.f + expf(-ctrl[b * 3 + 2]));
            float inv = 1.f / (g0 + g1 + g2 + 1e-6f);
            push[q] = g0 * inv; pop[q] = g1 * inv; stay[q] = g2 * inv;
        }

        if (tid < 32) sPtr[tid] = ptrv[b0 * 16 + tid];   // [q*16+t]

        // mem_new blend for BOTH batches, float4 vectorized (1024 float4 total)
#pragma unroll
        for (int it = 0; it < 4; ++it) {
            int i4 = tid + it * 256;          // 0..1023
            int q  = i4 >> 9;                 // batch within pair
            int j  = (i4 & 511) * 4;          // 0..2044, element offset
            int s_ = j >> 7, d2 = j & 127;
            int b  = b0 + q;
            float4 mv = *reinterpret_cast<const float4*>(mem + b * 2048 + j);
            const float* zp = (d2 < 64) ? (zr + b * 64 + d2) : (zi + b * 64 + (d2 - 64));
            float4 zv = *reinterpret_cast<const float4*>(zp);
            float om = 1.f - push[q], p = push[q];
            float4 nv;
            nv.x = mv.x * om + p * zv.x;
            nv.y = mv.y * om + p * zv.y;
            nv.z = mv.z * om + p * zv.z;
            nv.w = mv.w * om + p * zv.w;
            *reinterpret_cast<float4*>(out + o_mem + b * 2048 + j) = nv;
            int dd = (d2 < 64) ? d2 : (d2 - 64);
            float* dst = ((d2 < 64) ? sMr : sMi) + q * 1056 + s_ * 66 + dd;
            dst[0] = nv.x; dst[1] = nv.y; dst[2] = nv.z; dst[3] = nv.w;
            if (d2 >= 64) {
                float* dn = sMn + q * 1056 + s_ * 66 + dd;
                dn[0] = -nv.x; dn[1] = -nv.y; dn[2] = -nv.z; dn[3] = -nv.w;
            }
        }
        __syncthreads();

        // new_ptr (roll-mix) + slot count for both batches (warp 0)
        if (tid < 32) {
            int q = tid >> 4, t = tid & 15, b = b0 + q;
            float np = push[q] * sPtr[q * 16 + ((t + 15) & 15)]
                     + pop[q]  * sPtr[q * 16 + ((t + 1) & 15)]
                     + stay[q] * sPtr[q * 16 + t];
            sNp[tid] = np;
            out[o_ptr + b * 16 + t] = np;
            unsigned bal = __ballot_sync(0xFFFFFFFFu, np > 0.1f);
            if (tid == 0) cnt += __popc(bal);
        }

        // ---- P = M * C (complex), packed-over-d f32x2, 2 batches share C loads ----
        // thread -> (s=sg, cols e = ln + 16k, k=0..3), both batches
        unsigned long long apr[2][4] = {{0,0,0,0},{0,0,0,0}};
        unsigned long long api[2][4] = {{0,0,0,0},{0,0,0,0}};
#pragma unroll 4
        for (int d2 = 0; d2 < 32; ++d2) {
            const float* crow = sCr + d2 * 128 + 2 * ln;
            const float* cirow = sCi + d2 * 128 + 2 * ln;
            unsigned long long c0r = L64(crow);       unsigned long long c0i = L64(cirow);
            unsigned long long c1r = L64(crow + 32);  unsigned long long c1i = L64(cirow + 32);
            unsigned long long c2r = L64(crow + 64);  unsigned long long c2i = L64(cirow + 64);
            unsigned long long c3r = L64(crow + 96);  unsigned long long c3i = L64(cirow + 96);
#pragma unroll
            for (int q = 0; q < 2; ++q) {
                int mo = q * 1056 + sg * 66 + 2 * d2;
                unsigned long long m_r = L64(sMr + mo);
                unsigned long long m_i = L64(sMi + mo);
                unsigned long long m_n = L64(sMn + mo);
                ffma2(apr[q][0], m_r, c0r); ffma2(apr[q][0], m_n, c0i);
                ffma2(api[q][0], m_r, c0i); ffma2(api[q][0], m_i, c0r);
                ffma2(apr[q][1], m_r, c1r); ffma2(apr[q][1], m_n, c1i);
                ffma2(api[q][1], m_r, c1i); ffma2(api[q][1], m_i, c1r);
                ffma2(apr[q][2], m_r, c2r); ffma2(apr[q][2], m_n, c2i);
                ffma2(api[q][2], m_r, c2i); ffma2(api[q][2], m_i, c2r);
                ffma2(apr[q][3], m_r, c3r); ffma2(apr[q][3], m_n, c3i);
                ffma2(api[q][3], m_r, c3i); ffma2(api[q][3], m_i, c3r);
            }
        }
#pragma unroll
        for (int q = 0; q < 2; ++q)
#pragma unroll
            for (int k = 0; k < 4; ++k) {
                sPr[q * 1056 + sg * 66 + ln + 16 * k] = hadd2(apr[q][k]);
                sPi[q * 1056 + sg * 66 + ln + 16 * k] = hadd2(api[q][k]);
            }
        __syncthreads();

        // ---- scores + softmax for both batches ----
#pragma unroll
        for (int q = 0; q < 2; ++q) {
            const float* pr = sPr + q * 1056 + sg * 66;
            const float* pi = sPi + q * 1056 + sg * 66;
            const float* mr = sMr + q * 1056 + ln * 66;
            const float* mi = sMi + q * 1056 + ln * 66;
            unsigned long long acc = 0;
#pragma unroll 8
            for (int d2 = 0; d2 < 32; ++d2) {
                ffma2(acc, L64(pr + 2 * d2), L64(mr + 2 * d2));
                ffma2(acc, L64(pi + 2 * d2), L64(mi + 2 * d2));
            }
            float sc = hadd2(acc) * 0.125f;   // D^-0.5
            float mx = sc;
            mx = fmaxf(mx, __shfl_xor_sync(0xFFFFFFFFu, mx, 8, 16));
            mx = fmaxf(mx, __shfl_xor_sync(0xFFFFFFFFu, mx, 4, 16));
            mx = fmaxf(mx, __shfl_xor_sync(0xFFFFFFFFu, mx, 2, 16));
            mx = fmaxf(mx, __shfl_xor_sync(0xFFFFFFFFu, mx, 1, 16));
            float ex = expf(sc - mx);
            float sme = ex;
            sme += __shfl_xor_sync(0xFFFFFFFFu, sme, 8, 16);
            sme += __shfl_xor_sync(0xFFFFFFFFu, sme, 4, 16);
            sme += __shfl_xor_sync(0xFFFFFFFFu, sme, 2, 16);
            sme += __shfl_xor_sync(0xFFFFFFFFu, sme, 1, 16);
            sAttn[q * 272 + sg * 17 + ln] = ex / sme;
        }
        __syncthreads();

        // cw[t] = sum_s np[s] * attn[s,t] (both batches, warp 0)
        if (tid < 32) {
            int q = tid >> 4, t = tid & 15;
            float a = 0.f;
#pragma unroll
            for (int s2 = 0; s2 < 16; ++s2)
                a = fmaf(sNp[q * 16 + s2], sAttn[q * 272 + s2 * 17 + t], a);
            sCw[tid] = a;
        }
        __syncthreads();

        // u[d] = sum_t cw[t] * M[t,d] (real|imag, both batches: 2*128 = 256 threads)
        {
            int q = tid >> 7, idx = tid & 127;
            int ri = idx >> 6, d2 = idx & 63;
            const float* Mrow = ((ri == 0) ? sMr : sMi) + q * 1056;
            float a = 0.f;
#pragma unroll
            for (int t2 = 0; t2 < 16; ++t2)
                a = fmaf(sCw[q * 16 + t2], Mrow[t2 * 66 + d2], a);
            g_U[(b0 + q) * 128 + ri * 64 + d2] = a;
        }
    }
    if (tid == 0) atomicAdd(&g_count, cnt);
}

// ---------------- kernel 2: z_read = u * Wv^T (complex, f32x2) ----------------
__global__ __launch_bounds__(256) void k_read(const float* __restrict__ wvr,
                                              const float* __restrict__ wvi,
                                              float* __restrict__ out, int o_zi)
{
    __shared__ float sWr[64 * 66];
    __shared__ float sWi[64 * 66];
    __shared__ float sU[16 * 128];
    __shared__ float sUn[16 * 64];

    const int tid = threadIdx.x;
    for (int i = tid; i < 4096; i += 256) {
        int r = i >> 6, c = i & 63;
        sWr[r * 66 + c] = wvr[i];
        sWi[r * 66 + c] = wvi[i];
    }
    const int b0 = blockIdx.x * 16;
    for (int i = tid; i < 2048; i += 256) {
        float v = g_U[b0 * 128 + i];
        sU[i] = v;
        int loc = i & 127;
        if (loc >= 64) sUn[(i >> 7) * 64 + (loc - 64)] = -v;
    }
    __syncthreads();

    const int bl = tid >> 4;   // local batch 0..15
    const int ln = tid & 15;   // j group
    unsigned long long rr[4] = {0, 0, 0, 0}, ri[4] = {0, 0, 0, 0};
#pragma unroll 4
    for (int d2 = 0; d2 < 32; ++d2) {
        unsigned long long ur = L64(sU + bl * 128 + 2 * d2);
        unsigned long long ui = L64(sU + bl * 128 + 64 + 2 * d2);
        unsigned long long un = L64(sUn + bl * 64 + 2 * d2);
#pragma unroll
        for (int k = 0; k < 4; ++k) {
            int j = ln + 16 * k;
            unsigned long long wr = L64(sWr + j * 66 + 2 * d2);
            unsigned long long wi = L64(sWi + j * 66 + 2 * d2);
            ffma2(rr[k], ur, wr); ffma2(rr[k], un, wi);
            ffma2(ri[k], ui, wr); ffma2(ri[k], ur, wi);
        }
    }
    const int b = b0 + bl;
#pragma unroll
    for (int k = 0; k < 4; ++k) {
        out[b * 64 + ln + 16 * k]        = hadd2(rr[k]);
        out[o_zi + b * 64 + ln + 16 * k] = hadd2(ri[k]);
    }
}

// ---------------- kernel 3: active_slots scalar ----------------
__global__ void k_final(float* __restrict__ out, int o_scal, float invB) {
    out[o_scal] = (float)g_count * invB;
}

// ---------------- launch ----------------
extern "C" void kernel_launch(void* const* d_in, const int* in_sizes, int n_in,
                              void* d_out, int out_size) {
    const float* zr   = (const float*)d_in[0];
    const float* zi   = (const float*)d_in[1];
    const float* mem  = (const float*)d_in[2];
    const float* ptrv = (const float*)d_in[3];
    const float* ctrl = (const float*)d_in[4];
    const float* wqr  = (const float*)d_in[5];
    const float* wqi  = (const float*)d_in[6];
    const float* wkr  = (const float*)d_in[7];
    const float* wki  = (const float*)d_in[8];
    const float* wvr  = (const float*)d_in[9];
    const float* wvi  = (const float*)d_in[10];
    float* out = (float*)d_out;

    const int B = in_sizes[0] / 64;               // 16384
    const int o_mem  = 2 * B * 64;                // after z_read_real|imag
    const int o_ptr  = o_mem + B * 2048;          // after mem_new
    const int o_scal = o_ptr + B * 16;            // active_slots scalar

    const int smem_bytes = (4096 * 2 + 5 * 2112 + 544 + 96) * (int)sizeof(float);
    cudaFuncSetAttribute(k_main, cudaFuncAttributeMaxDynamicSharedMemorySize, smem_bytes);

    k_prep<<<64, 64>>>(wqr, wqi, wkr, wki);
    k_main<<<B / NB, 256, smem_bytes>>>(zr, zi, mem, ptrv, ctrl, out, o_mem, o_ptr);
    k_read<<<B / 16, 256>>>(wvr, wvi, out, B * 64);
    k_final<<<1, 1>>>(out, o_scal, 1.f / (float)B);
}